// round 8
// baseline (speedup 1.0000x reference)
#include <cuda_runtime.h>
#include <cstdint>

#define N_BATCH 8
#define K_ANCH  9
#define Hdim    120
#define Wdim    120
#define HW      (Hdim*Wdim)
#define TOT     (HW*K_ANCH)       /* 129600 */
#define PRE     3000
#define POST    300
#define NWORDS  47                /* ceil(3000/64) */
#define MPITCH  48
#define NPAIR   24                /* ceil(47/2) word-pairs (128 bits each) */
#define CAND_MAX 8192
#define NBUCKET  4096

// ---------------- scratch (static device globals; no allocation) ------------
__device__ int    g_topk_idx[N_BATCH*PRE];
__device__ float  g_topk_score[N_BATCH*PRE];
__device__ float4 g_boxes[N_BATCH*PRE];
__device__ unsigned long long g_mask[(size_t)N_BATCH*PRE*MPITCH];   // ~9.2MB
__device__ float  g_selscore[N_BATCH*POST];

// monotone float->uint key (descending floats -> descending uints)
__device__ __forceinline__ unsigned int fkey(float x) {
    unsigned int u = __float_as_uint(x);
    return (u & 0x80000000u) ? ~u : (u | 0x80000000u);
}
__device__ __forceinline__ float fkey_inv(unsigned int k) {
    return (k & 0x80000000u) ? __uint_as_float(k ^ 0x80000000u)
                             : __uint_as_float(~k);
}

// ---------------- Stage 1+2: per-batch exact top-3000 + box gather ----------
extern "C" __global__ void __launch_bounds__(1024)
topk_kernel(const float* __restrict__ cls, const float* __restrict__ deltas) {
    extern __shared__ unsigned long long s_cand[];   // 8192 * 8B = 64KB
    __shared__ unsigned int hist[NBUCKET];           // 16KB
    __shared__ unsigned int psum[1024];              // 4KB
    __shared__ unsigned int s_B;
    __shared__ unsigned int s_cnt;

    const int n   = blockIdx.x;
    const int tid = threadIdx.x;
    const float* sc = cls + (size_t)n * TOT;
    const float4* sc4 = (const float4*)sc;

    for (int b = tid; b < NBUCKET; b += 1024) hist[b] = 0;
    if (tid == 0) s_cnt = 0;
    __syncthreads();

    for (int i = tid; i < TOT/4; i += 1024) {
        float4 v = sc4[i];
        atomicAdd(&hist[fkey(v.x) >> 20], 1u);
        atomicAdd(&hist[fkey(v.y) >> 20], 1u);
        atomicAdd(&hist[fkey(v.z) >> 20], 1u);
        atomicAdd(&hist[fkey(v.w) >> 20], 1u);
    }
    __syncthreads();

    psum[tid] = hist[4*tid] + hist[4*tid+1] + hist[4*tid+2] + hist[4*tid+3];
    __syncthreads();

    if (tid == 0) {
        unsigned int acc = 0;
        int S = 0;
        for (int s = 31; s >= 0; --s) {
            unsigned int q = 0;
            for (int t = 0; t < 32; ++t) q += psum[s*32 + t];
            if (acc + q >= PRE) { S = s; break; }
            acc += q;
        }
        int Pb = S*32;
        for (int t = 31; t >= 0; --t) {
            unsigned int q = psum[S*32 + t];
            if (acc + q >= PRE) { Pb = S*32 + t; break; }
            acc += q;
        }
        unsigned int B = (unsigned int)(Pb*4);
        for (int b = 3; b >= 0; --b) {
            unsigned int q = hist[Pb*4 + b];
            if (acc + q >= PRE) { B = (unsigned int)(Pb*4 + b); break; }
            acc += q;
        }
        s_B = B;
    }
    __syncthreads();

    const unsigned int thr = s_B << 20;
    for (int i = tid; i < TOT/4; i += 1024) {
        float4 v = sc4[i];
        float vv[4] = {v.x, v.y, v.z, v.w};
#pragma unroll
        for (int c = 0; c < 4; ++c) {
            unsigned int k = fkey(vv[c]);
            if (k >= thr) {
                unsigned int pos = atomicAdd(&s_cnt, 1u);
                if (pos < CAND_MAX)
                    s_cand[pos] = ((unsigned long long)k << 32) |
                                  (unsigned int)(~(unsigned int)(4*i + c));
            }
        }
    }
    __syncthreads();

    const unsigned int cnt = s_cnt;               // guaranteed >= PRE
    const int S_sort = (cnt <= 4096u) ? 4096 : 8192;
    for (int i = (int)cnt + tid; i < S_sort; i += 1024) s_cand[i] = 0ull;
    __syncthreads();

    // bitonic sort, descending on u64 (ties: smaller idx first via ~idx)
    for (int k = 2; k <= S_sort; k <<= 1) {
        for (int j = k >> 1; j > 0; j >>= 1) {
            for (int i = tid; i < S_sort; i += 1024) {
                int ixj = i ^ j;
                if (ixj > i) {
                    unsigned long long a = s_cand[i], b = s_cand[ixj];
                    bool dir = (i & k) != 0;
                    if ((a < b) != dir) { s_cand[i] = b; s_cand[ixj] = a; }
                }
            }
            __syncthreads();
        }
    }

    // output scores + fused box gather-compute
    const float ratios_[3] = {0.5f, 1.0f, 2.0f};
    const float scales_[3] = {8.0f, 16.0f, 32.0f};
    for (int r = tid; r < PRE; r += 1024) {
        unsigned long long c = s_cand[r];
        unsigned int key = (unsigned int)(c >> 32);
        int o = (int)(~(unsigned int)(c & 0xFFFFFFFFull));
        g_topk_score[n*PRE + r] = fkey_inv(key);

        const int kk = o % K_ANCH;
        const int t0 = o / K_ANCH;
        const int ww = t0 % Wdim;
        const int hh = t0 / Wdim;

        float v[4];
#pragma unroll
        for (int jj = 0; jj < 4; ++jj) {
            int f  = ((kk*4 + jj)*Hdim + hh)*Wdim + ww;
            int j  = f & 3;
            int r1 = f >> 2;
            int k  = r1 % K_ANCH;
            int r2 = r1 / K_ANCH;
            int w  = r2 % Wdim;
            int h  = r2 / Wdim;

            float sr  = __fsqrt_rn(ratios_[k/3]);
            float wsz = __fdiv_rn(__fmul_rn(16.0f, scales_[k%3]), sr);
            float hsz = __fmul_rn(__fmul_rn(16.0f, scales_[k%3]), sr);
            float cx  = __fmul_rn(__fadd_rn((float)w, 0.5f), 16.0f);
            float cy  = __fmul_rn(__fadd_rn((float)h, 0.5f), 16.0f);

            float a;
            if      (j == 0) a = __fsub_rn(cx, __fmul_rn(0.5f, wsz));
            else if (j == 1) a = __fsub_rn(cy, __fmul_rn(0.5f, hsz));
            else if (j == 2) a = __fadd_rn(cx, __fmul_rn(0.5f, wsz));
            else             a = __fadd_rn(cy, __fmul_rn(0.5f, hsz));

            float d   = deltas[((size_t)n*36 + (k*4 + j))*HW + h*Wdim + w];
            float val = __fadd_rn(a, d);
            v[jj] = fminf(fmaxf(val, 0.0f), 1919.0f);
        }
        g_boxes[n*PRE + r] = make_float4(v[0], v[1], v[2], v[3]);
    }
}

// ---------------- Stage 3: NMS suppression bitmask (fdiv, R1-proven) --------
extern "C" __global__ void mask_kernel() {
    const int rb = blockIdx.x, cb = blockIdx.y, n = blockIdx.z;
    if (cb < rb) return;
    __shared__ float4 colbox[64];
    __shared__ float  colarea[64];
    const int tid = threadIdx.x;
    const int cj = cb*64 + tid;
    float4 cbx = (cj < PRE) ? g_boxes[n*PRE + cj] : make_float4(0,0,0,0);
    colbox[tid] = cbx;
    colarea[tid] = __fmul_rn(__fadd_rn(__fsub_rn(cbx.z, cbx.x), 1.0f),
                             __fadd_rn(__fsub_rn(cbx.w, cbx.y), 1.0f));
    __syncthreads();

    const int i = rb*64 + tid;
    if (i >= PRE) return;
    const float4 bi = g_boxes[n*PRE + i];
    const float ai = __fmul_rn(__fadd_rn(__fsub_rn(bi.z, bi.x), 1.0f),
                               __fadd_rn(__fsub_rn(bi.w, bi.y), 1.0f));
    unsigned long long bits = 0ull;
    const int jmax = min(64, PRE - cb*64);
    for (int c = 0; c < jmax; ++c) {
        int j = cb*64 + c;
        if (j <= i) continue;
        float4 bj = colbox[c];
        float aj = colarea[c];
        float xx1 = fmaxf(bi.x, bj.x), yy1 = fmaxf(bi.y, bj.y);
        float xx2 = fminf(bi.z, bj.z), yy2 = fminf(bi.w, bj.w);
        float iw = fmaxf(__fadd_rn(__fsub_rn(xx2, xx1), 1.0f), 0.0f);
        float ih = fmaxf(__fadd_rn(__fsub_rn(yy2, yy1), 1.0f), 0.0f);
        float inter = __fmul_rn(iw, ih);
        float denom = __fsub_rn(__fadd_rn(ai, aj), inter);
        float iou   = __fdiv_rn(inter, denom);
        if (iou > 0.5f) bits |= (1ull << c);
    }
    g_mask[((size_t)n*PRE + i)*MPITCH + cb] = bits;
}

// ---------------- Stage 4: lazy scan, 128-bit blocks, MLP'd gather ----------
// One warp per batch; 24 word-pair iterations. Suppression OR for pair t =
// OR over kept rows' 16B (ulonglong2) entries, gathered with 4 independent
// accumulator pairs (MLP>=4), shfl-reduced. Intra-pair greedy resolved from
// the prefetched 128-row diagonal block (ping-pong smem). Word 47 is garbage
// but fully masked by full1 = 0 on the last pair.
extern "C" __global__ void __launch_bounds__(32)
scan_kernel(float* __restrict__ out) {
    const int n = blockIdx.x;
    const int lane = threadIdx.x;
    __shared__ ulonglong2 s_diag[2][128];    // 4KB
    __shared__ int s_kept[POST];
    const unsigned FULL = 0xffffffffu;

    const unsigned long long* __restrict__ mbase =
        g_mask + (size_t)n * PRE * MPITCH;

    // preload diagonal block of pair 0 (rows 0..127, words 0..1)
#pragma unroll
    for (int q = 0; q < 4; ++q) {
        int r = lane + 32*q;
        s_diag[0][r] = *(const ulonglong2*)(mbase + (size_t)r * MPITCH);
    }
    __syncwarp();

    int nk = 0;
    for (int t = 0; t < NPAIR && nk < POST; ++t) {
        const int cb = t & 1, pb = cb ^ 1;
        const int w2 = 2*t;

        // prefetch diagonal block of pair t+1
        if (t + 1 < NPAIR) {
#pragma unroll
            for (int q = 0; q < 4; ++q) {
                int r = 128*(t+1) + lane + 32*q;
                ulonglong2 d = make_ulonglong2(0ull, 0ull);
                if (r < PRE)
                    d = *(const ulonglong2*)(mbase + (size_t)r * MPITCH + (w2+2));
                s_diag[pb][lane + 32*q] = d;
            }
        }

        // lazy suppression OR: 4 independent accumulator pairs (MLP)
        unsigned long long x0=0,y0=0,x1=0,y1=0,x2=0,y2=0,x3=0,y3=0;
        int j = lane;
        for (; j + 96 < nk; j += 128) {
            ulonglong2 m0 = *(const ulonglong2*)(mbase + (size_t)s_kept[j     ]*MPITCH + w2);
            ulonglong2 m1 = *(const ulonglong2*)(mbase + (size_t)s_kept[j + 32]*MPITCH + w2);
            ulonglong2 m2 = *(const ulonglong2*)(mbase + (size_t)s_kept[j + 64]*MPITCH + w2);
            ulonglong2 m3 = *(const ulonglong2*)(mbase + (size_t)s_kept[j + 96]*MPITCH + w2);
            x0 |= m0.x; y0 |= m0.y;
            x1 |= m1.x; y1 |= m1.y;
            x2 |= m2.x; y2 |= m2.y;
            x3 |= m3.x; y3 |= m3.y;
        }
        for (; j < nk; j += 32) {
            ulonglong2 m = *(const ulonglong2*)(mbase + (size_t)s_kept[j]*MPITCH + w2);
            x0 |= m.x; y0 |= m.y;
        }
        unsigned long long a0 = (x0|x1)|(x2|x3);
        unsigned long long a1 = (y0|y1)|(y2|y3);
#pragma unroll
        for (int off = 16; off; off >>= 1) {
            a0 |= __shfl_xor_sync(FULL, a0, off);
            a1 |= __shfl_xor_sync(FULL, a1, off);
        }

        unsigned long long f0 = (w2   == NWORDS-1) ? ((1ull<<56)-1ull)
                              : (w2   <  NWORDS  ) ? ~0ull : 0ull;
        unsigned long long f1 = (w2+1 == NWORDS-1) ? ((1ull<<56)-1ull)
                              : (w2+1 <  NWORDS  ) ? ~0ull : 0ull;
        unsigned long long c0 = f0 & ~a0;
        unsigned long long c1 = f1 & ~a1;

        // serial intra-pair greedy resolve (uniform; smem only)
        const int base = 128*t;
        while ((c0 | c1) && nk < POST) {
            if (c0) {
                int b = __ffsll((long long)c0) - 1;
                s_kept[nk] = base + b;
                ++nk;
                c0 &= ~(1ull << b);
                ulonglong2 d = s_diag[cb][b];
                c0 &= ~d.x;
                c1 &= ~d.y;
            } else {
                int b = __ffsll((long long)c1) - 1;
                s_kept[nk] = base + 64 + b;
                ++nk;
                c1 &= ~(1ull << b);
                ulonglong2 d = s_diag[cb][64 + b];
                c1 &= ~d.y;      // d.x covers word 2t: all cols < row, zero
            }
        }
        __syncwarp();
    }
    __syncwarp();

    for (int r = lane; r < POST; r += 32) {
        float sc = 0.0f, x1 = 0.0f, y1 = 0.0f, x2 = 0.0f, y2 = 0.0f;
        if (r < nk) {
            int i = s_kept[r];
            float4 b = g_boxes[n*PRE + i];
            x1 = b.x; y1 = b.y; x2 = b.z; y2 = b.w;
            sc = g_topk_score[n*PRE + i];
        }
        float* o = out + (size_t)(n*POST + r)*5;
        o[1] = x1; o[2] = y1; o[3] = x2; o[4] = y2;
        g_selscore[n*POST + r] = sc;
    }
}

// ---------------- Stage 5: score column = batch 7's selected scores ---------
extern "C" __global__ void final_kernel(float* __restrict__ out) {
    int g = blockIdx.x*blockDim.x + threadIdx.x;
    if (g >= N_BATCH*POST) return;
    int r = g % POST;
    out[(size_t)g*5] = g_selscore[7*POST + r];
}

// ---------------- launch -----------------------------------------------------
extern "C" void kernel_launch(void* const* d_in, const int* in_sizes, int n_in,
                              void* d_out, int out_size) {
    const float* cls;
    const float* deltas;
    if (in_sizes[0] == N_BATCH*K_ANCH*HW) {     // 1,036,800
        cls = (const float*)d_in[0]; deltas = (const float*)d_in[1];
    } else {
        cls = (const float*)d_in[1]; deltas = (const float*)d_in[0];
    }
    float* out = (float*)d_out;

    cudaFuncSetAttribute(topk_kernel,
                         cudaFuncAttributeMaxDynamicSharedMemorySize, 65536);

    topk_kernel<<<N_BATCH, 1024, 65536>>>(cls, deltas);
    dim3 mg(NWORDS, NWORDS, N_BATCH);
    mask_kernel<<<mg, 64>>>();
    scan_kernel<<<N_BATCH, 32>>>(out);
    final_kernel<<<(N_BATCH*POST + 255)/256, 256>>>(out);
}

// round 9
// speedup vs baseline: 1.2893x; 1.2893x over previous
#include <cuda_runtime.h>
#include <cstdint>

#define N_BATCH 8
#define K_ANCH  9
#define Hdim    120
#define Wdim    120
#define HW      (Hdim*Wdim)
#define TOT     (HW*K_ANCH)       /* 129600 */
#define PRE     3000
#define POST    300
#define NWORDS  47                /* ceil(3000/64) */
#define MPITCH  48
#define NPAIR   24                /* ceil(47/2) word-pairs (128 bits each) */
#define CAND_MAX 8192
#define NBUCKET  4096

// ---------------- scratch (static device globals; no allocation) ------------
__device__ float  g_topk_score[N_BATCH*PRE];
__device__ float4 g_boxes[N_BATCH*PRE];
__device__ unsigned long long g_mask[(size_t)N_BATCH*PRE*MPITCH];   // ~9.2MB

// monotone float->uint key (descending floats -> descending uints)
__device__ __forceinline__ unsigned int fkey(float x) {
    unsigned int u = __float_as_uint(x);
    return (u & 0x80000000u) ? ~u : (u | 0x80000000u);
}
__device__ __forceinline__ float fkey_inv(unsigned int k) {
    return (k & 0x80000000u) ? __uint_as_float(k ^ 0x80000000u)
                             : __uint_as_float(~k);
}
__device__ __forceinline__ float boxarea(float4 b) {
    return __fmul_rn(__fadd_rn(__fsub_rn(b.z, b.x), 1.0f),
                     __fadd_rn(__fsub_rn(b.w, b.y), 1.0f));
}

// exact fp32 test for  RN(inter/denom) > 0.5  without division.
// 2i and d*2^-24 are exact (power-of-2 scale); RN(2i-d) is exact in the
// ambiguity band (Sterbenz) and sign-robust outside it.
__device__ __forceinline__ bool iou_gt_half(float inter, float denom) {
    float t = __fsub_rn(__fadd_rn(inter, inter), denom);
    bool pos = (t > __fmul_rn(denom, 0x1p-24f));
    return (denom > 0.0f) ? pos : ((denom == 0.0f) & (inter > 0.0f));
}

// ---------------- Stage 1+2: per-batch exact top-3000 + box gather ----------
extern "C" __global__ void __launch_bounds__(1024)
topk_kernel(const float* __restrict__ cls, const float* __restrict__ deltas) {
    extern __shared__ unsigned long long s_cand[];   // 8192 * 8B = 64KB
    __shared__ unsigned int hist[NBUCKET];           // 16KB
    __shared__ unsigned int psum[1024];              // 4KB
    __shared__ unsigned int s_B;
    __shared__ unsigned int s_cnt;

    const int n   = blockIdx.x;
    const int tid = threadIdx.x;
    const float* sc = cls + (size_t)n * TOT;
    const float4* sc4 = (const float4*)sc;

    for (int b = tid; b < NBUCKET; b += 1024) hist[b] = 0;
    if (tid == 0) s_cnt = 0;
    __syncthreads();

    for (int i = tid; i < TOT/4; i += 1024) {
        float4 v = sc4[i];
        atomicAdd(&hist[fkey(v.x) >> 20], 1u);
        atomicAdd(&hist[fkey(v.y) >> 20], 1u);
        atomicAdd(&hist[fkey(v.z) >> 20], 1u);
        atomicAdd(&hist[fkey(v.w) >> 20], 1u);
    }
    __syncthreads();

    psum[tid] = hist[4*tid] + hist[4*tid+1] + hist[4*tid+2] + hist[4*tid+3];
    __syncthreads();

    if (tid == 0) {
        unsigned int acc = 0;
        int S = 0;
        for (int s = 31; s >= 0; --s) {
            unsigned int q = 0;
            for (int t = 0; t < 32; ++t) q += psum[s*32 + t];
            if (acc + q >= PRE) { S = s; break; }
            acc += q;
        }
        int Pb = S*32;
        for (int t = 31; t >= 0; --t) {
            unsigned int q = psum[S*32 + t];
            if (acc + q >= PRE) { Pb = S*32 + t; break; }
            acc += q;
        }
        unsigned int B = (unsigned int)(Pb*4);
        for (int b = 3; b >= 0; --b) {
            unsigned int q = hist[Pb*4 + b];
            if (acc + q >= PRE) { B = (unsigned int)(Pb*4 + b); break; }
            acc += q;
        }
        s_B = B;
    }
    __syncthreads();

    const unsigned int thr = s_B << 20;
    for (int i = tid; i < TOT/4; i += 1024) {
        float4 v = sc4[i];
        float vv[4] = {v.x, v.y, v.z, v.w};
#pragma unroll
        for (int c = 0; c < 4; ++c) {
            unsigned int k = fkey(vv[c]);
            if (k >= thr) {
                unsigned int pos = atomicAdd(&s_cnt, 1u);
                if (pos < CAND_MAX)
                    s_cand[pos] = ((unsigned long long)k << 32) |
                                  (unsigned int)(~(unsigned int)(4*i + c));
            }
        }
    }
    __syncthreads();

    const unsigned int cnt = s_cnt;               // guaranteed >= PRE
    const int S_sort = (cnt <= 4096u) ? 4096 : 8192;
    for (int i = (int)cnt + tid; i < S_sort; i += 1024) s_cand[i] = 0ull;
    __syncthreads();

    // bitonic sort, descending on u64 (ties: smaller idx first via ~idx)
    for (int k = 2; k <= S_sort; k <<= 1) {
        for (int j = k >> 1; j > 0; j >>= 1) {
            for (int i = tid; i < S_sort; i += 1024) {
                int ixj = i ^ j;
                if (ixj > i) {
                    unsigned long long a = s_cand[i], b = s_cand[ixj];
                    bool dir = (i & k) != 0;
                    if ((a < b) != dir) { s_cand[i] = b; s_cand[ixj] = a; }
                }
            }
            __syncthreads();
        }
    }

    // output scores + fused box gather-compute
    const float ratios_[3] = {0.5f, 1.0f, 2.0f};
    const float scales_[3] = {8.0f, 16.0f, 32.0f};
    for (int r = tid; r < PRE; r += 1024) {
        unsigned long long c = s_cand[r];
        unsigned int key = (unsigned int)(c >> 32);
        int o = (int)(~(unsigned int)(c & 0xFFFFFFFFull));
        g_topk_score[n*PRE + r] = fkey_inv(key);

        const int kk = o % K_ANCH;
        const int t0 = o / K_ANCH;
        const int ww = t0 % Wdim;
        const int hh = t0 / Wdim;

        float v[4];
#pragma unroll
        for (int jj = 0; jj < 4; ++jj) {
            int f  = ((kk*4 + jj)*Hdim + hh)*Wdim + ww;
            int j  = f & 3;
            int r1 = f >> 2;
            int k  = r1 % K_ANCH;
            int r2 = r1 / K_ANCH;
            int w  = r2 % Wdim;
            int h  = r2 / Wdim;

            float sr  = __fsqrt_rn(ratios_[k/3]);
            float wsz = __fdiv_rn(__fmul_rn(16.0f, scales_[k%3]), sr);
            float hsz = __fmul_rn(__fmul_rn(16.0f, scales_[k%3]), sr);
            float cx  = __fmul_rn(__fadd_rn((float)w, 0.5f), 16.0f);
            float cy  = __fmul_rn(__fadd_rn((float)h, 0.5f), 16.0f);

            float a;
            if      (j == 0) a = __fsub_rn(cx, __fmul_rn(0.5f, wsz));
            else if (j == 1) a = __fsub_rn(cy, __fmul_rn(0.5f, hsz));
            else if (j == 2) a = __fadd_rn(cx, __fmul_rn(0.5f, wsz));
            else             a = __fadd_rn(cy, __fmul_rn(0.5f, hsz));

            float d   = deltas[((size_t)n*36 + (k*4 + j))*HW + h*Wdim + w];
            float val = __fadd_rn(a, d);
            v[jj] = fminf(fmaxf(val, 0.0f), 1919.0f);
        }
        g_boxes[n*PRE + r] = make_float4(v[0], v[1], v[2], v[3]);
    }
}

// ---------------- Stage 3: NMS suppression bitmask ---------------------------
// 256 threads cover 4 row-blocks x 1 column-block; colbox smem shared.
// Off-diagonal tiles: branch-free inner loop. Division-free exact IoU test.
extern "C" __global__ void __launch_bounds__(256)
mask_kernel() {
    const int cb = blockIdx.y, n = blockIdx.z;
    const int sub = threadIdx.x >> 6;            // 0..3
    const int t   = threadIdx.x & 63;
    const int rb  = blockIdx.x*4 + sub;
    __shared__ float4 colbox[64];
    __shared__ float  colarea[64];

    if (threadIdx.x < 64) {
        int cj = cb*64 + threadIdx.x;
        float4 cbx = (cj < PRE) ? g_boxes[n*PRE + cj] : make_float4(0,0,0,0);
        colbox[threadIdx.x]  = cbx;
        colarea[threadIdx.x] = boxarea(cbx);
    }
    __syncthreads();

    if (rb > cb || rb >= NWORDS) return;
    const int i = rb*64 + t;
    if (i >= PRE) return;

    const float4 bi = g_boxes[n*PRE + i];
    const float  ai = boxarea(bi);
    const int jmax = min(64, PRE - cb*64);
    unsigned long long bits = 0ull;
    const int cstart = (rb == cb) ? (t + 1) : 0;

    for (int c = cstart; c < jmax; ++c) {
        float4 bj = colbox[c];
        float aj = colarea[c];
        float xx1 = fmaxf(bi.x, bj.x), yy1 = fmaxf(bi.y, bj.y);
        float xx2 = fminf(bi.z, bj.z), yy2 = fminf(bi.w, bj.w);
        float iw = fmaxf(__fadd_rn(__fsub_rn(xx2, xx1), 1.0f), 0.0f);
        float ih = fmaxf(__fadd_rn(__fsub_rn(yy2, yy1), 1.0f), 0.0f);
        float inter = __fmul_rn(iw, ih);
        float denom = __fsub_rn(__fadd_rn(ai, aj), inter);
        if (iou_gt_half(inter, denom)) bits |= (1ull << c);
    }
    g_mask[((size_t)n*PRE + i)*MPITCH + cb] = bits;
}

// ---------------- Stage 4: lazy scan, 128-bit blocks, MLP'd gather ----------
// One warp per batch; 24 word-pair iterations (see R8). Batch 7's block also
// writes the broadcast score column for ALL batches (replaces final_kernel).
extern "C" __global__ void __launch_bounds__(32)
scan_kernel(float* __restrict__ out) {
    const int n = blockIdx.x;
    const int lane = threadIdx.x;
    __shared__ ulonglong2 s_diag[2][128];    // 4KB
    __shared__ int s_kept[POST];
    const unsigned FULL = 0xffffffffu;

    const unsigned long long* __restrict__ mbase =
        g_mask + (size_t)n * PRE * MPITCH;

    // preload diagonal block of pair 0 (rows 0..127, words 0..1)
#pragma unroll
    for (int q = 0; q < 4; ++q) {
        int r = lane + 32*q;
        s_diag[0][r] = *(const ulonglong2*)(mbase + (size_t)r * MPITCH);
    }
    __syncwarp();

    int nk = 0;
    for (int t = 0; t < NPAIR && nk < POST; ++t) {
        const int cb = t & 1, pb = cb ^ 1;
        const int w2 = 2*t;

        // prefetch diagonal block of pair t+1
        if (t + 1 < NPAIR) {
#pragma unroll
            for (int q = 0; q < 4; ++q) {
                int r = 128*(t+1) + lane + 32*q;
                ulonglong2 d = make_ulonglong2(0ull, 0ull);
                if (r < PRE)
                    d = *(const ulonglong2*)(mbase + (size_t)r * MPITCH + (w2+2));
                s_diag[pb][lane + 32*q] = d;
            }
        }

        // lazy suppression OR: 4 independent accumulator pairs (MLP)
        unsigned long long x0=0,y0=0,x1=0,y1=0,x2=0,y2=0,x3=0,y3=0;
        int j = lane;
        for (; j + 96 < nk; j += 128) {
            ulonglong2 m0 = *(const ulonglong2*)(mbase + (size_t)s_kept[j     ]*MPITCH + w2);
            ulonglong2 m1 = *(const ulonglong2*)(mbase + (size_t)s_kept[j + 32]*MPITCH + w2);
            ulonglong2 m2 = *(const ulonglong2*)(mbase + (size_t)s_kept[j + 64]*MPITCH + w2);
            ulonglong2 m3 = *(const ulonglong2*)(mbase + (size_t)s_kept[j + 96]*MPITCH + w2);
            x0 |= m0.x; y0 |= m0.y;
            x1 |= m1.x; y1 |= m1.y;
            x2 |= m2.x; y2 |= m2.y;
            x3 |= m3.x; y3 |= m3.y;
        }
        for (; j < nk; j += 32) {
            ulonglong2 m = *(const ulonglong2*)(mbase + (size_t)s_kept[j]*MPITCH + w2);
            x0 |= m.x; y0 |= m.y;
        }
        unsigned long long a0 = (x0|x1)|(x2|x3);
        unsigned long long a1 = (y0|y1)|(y2|y3);
#pragma unroll
        for (int off = 16; off; off >>= 1) {
            a0 |= __shfl_xor_sync(FULL, a0, off);
            a1 |= __shfl_xor_sync(FULL, a1, off);
        }

        unsigned long long f0 = (w2   == NWORDS-1) ? ((1ull<<56)-1ull)
                              : (w2   <  NWORDS  ) ? ~0ull : 0ull;
        unsigned long long f1 = (w2+1 == NWORDS-1) ? ((1ull<<56)-1ull)
                              : (w2+1 <  NWORDS  ) ? ~0ull : 0ull;
        unsigned long long c0 = f0 & ~a0;
        unsigned long long c1 = f1 & ~a1;

        // serial intra-pair greedy resolve (uniform; smem only)
        const int base = 128*t;
        while ((c0 | c1) && nk < POST) {
            if (c0) {
                int b = __ffsll((long long)c0) - 1;
                s_kept[nk] = base + b;
                ++nk;
                c0 &= ~(1ull << b);
                ulonglong2 d = s_diag[cb][b];
                c0 &= ~d.x;
                c1 &= ~d.y;
            } else {
                int b = __ffsll((long long)c1) - 1;
                s_kept[nk] = base + 64 + b;
                ++nk;
                c1 &= ~(1ull << b);
                ulonglong2 d = s_diag[cb][64 + b];
                c1 &= ~d.y;      // d.x covers word 2t: all cols < row, zero
            }
        }
        __syncwarp();
    }
    __syncwarp();

    for (int r = lane; r < POST; r += 32) {
        float x1 = 0.0f, y1 = 0.0f, x2 = 0.0f, y2 = 0.0f;
        if (r < nk) {
            int i = s_kept[r];
            float4 b = g_boxes[n*PRE + i];
            x1 = b.x; y1 = b.y; x2 = b.z; y2 = b.w;
        }
        float* o = out + (size_t)(n*POST + r)*5;
        o[1] = x1; o[2] = y1; o[3] = x2; o[4] = y2;
    }

    // batch 7 broadcasts its selected scores into column 0 of every batch
    if (n == 7) {
        for (int r = lane; r < POST; r += 32) {
            float sc = (r < nk) ? g_topk_score[7*PRE + s_kept[r]] : 0.0f;
#pragma unroll
            for (int nn = 0; nn < N_BATCH; ++nn)
                out[(size_t)(nn*POST + r)*5] = sc;
        }
    }
}

// ---------------- launch -----------------------------------------------------
extern "C" void kernel_launch(void* const* d_in, const int* in_sizes, int n_in,
                              void* d_out, int out_size) {
    const float* cls;
    const float* deltas;
    if (in_sizes[0] == N_BATCH*K_ANCH*HW) {     // 1,036,800
        cls = (const float*)d_in[0]; deltas = (const float*)d_in[1];
    } else {
        cls = (const float*)d_in[1]; deltas = (const float*)d_in[0];
    }
    float* out = (float*)d_out;

    cudaFuncSetAttribute(topk_kernel,
                         cudaFuncAttributeMaxDynamicSharedMemorySize, 65536);

    topk_kernel<<<N_BATCH, 1024, 65536>>>(cls, deltas);
    dim3 mg((NWORDS + 3)/4, NWORDS, N_BATCH);
    mask_kernel<<<mg, 256>>>();
    scan_kernel<<<N_BATCH, 32>>>(out);
}

// round 10
// speedup vs baseline: 1.3635x; 1.0576x over previous
#include <cuda_runtime.h>
#include <cstdint>

#define N_BATCH 8
#define K_ANCH  9
#define Hdim    120
#define Wdim    120
#define HW      (Hdim*Wdim)
#define TOT     (HW*K_ANCH)       /* 129600 */
#define PRE     3000
#define POST    300
#define NWORDS  47                /* ceil(3000/64) */
#define MPITCH  48
#define NPAIR   24                /* ceil(47/2) word-pairs (128 bits each) */
#define CAND_MAX 8192
#define NBUCKET  4096
#define SMEM_DYN ((CAND_MAX + 4096) * 8)   /* s_cand[8192] + s_cand2[4096] */

// ---------------- scratch (static device globals; no allocation) ------------
__device__ float  g_topk_score[N_BATCH*PRE];
__device__ float4 g_boxes[N_BATCH*PRE];
__device__ unsigned long long g_mask[(size_t)N_BATCH*PRE*MPITCH];   // ~9.2MB

// monotone float->uint key (descending floats -> descending uints)
__device__ __forceinline__ unsigned int fkey(float x) {
    unsigned int u = __float_as_uint(x);
    return (u & 0x80000000u) ? ~u : (u | 0x80000000u);
}
__device__ __forceinline__ float fkey_inv(unsigned int k) {
    return (k & 0x80000000u) ? __uint_as_float(k ^ 0x80000000u)
                             : __uint_as_float(~k);
}
__device__ __forceinline__ float boxarea(float4 b) {
    return __fmul_rn(__fadd_rn(__fsub_rn(b.z, b.x), 1.0f),
                     __fadd_rn(__fsub_rn(b.w, b.y), 1.0f));
}
// exact fp32 test for RN(inter/denom) > 0.5 without division (R9-proven)
__device__ __forceinline__ bool iou_gt_half(float inter, float denom) {
    float t = __fsub_rn(__fadd_rn(inter, inter), denom);
    bool pos = (t > __fmul_rn(denom, 0x1p-24f));
    return (denom > 0.0f) ? pos : ((denom == 0.0f) & (inter > 0.0f));
}

// ---------------- Stage 1+2: top-3000 (refined threshold) + box gather ------
extern "C" __global__ void __launch_bounds__(1024)
topk_kernel(const float* __restrict__ cls, const float* __restrict__ deltas) {
    extern __shared__ unsigned long long s_cand[];        // [8192] + [4096]
    unsigned long long* s_cand2 = s_cand + CAND_MAX;
    __shared__ unsigned int hist[NBUCKET];                // 16KB (reused)
    __shared__ unsigned int psum[1024];                   // 4KB  (reused)
    __shared__ unsigned int s_B, s_F, s_accAbove, s_newcnt;
    __shared__ unsigned int s_cnt, s_cnt2;

    const int n   = blockIdx.x;
    const int tid = threadIdx.x;
    const float4* sc4 = (const float4*)(cls + (size_t)n * TOT);

    for (int b = tid; b < NBUCKET; b += 1024) hist[b] = 0;
    if (tid == 0) { s_cnt = 0; s_cnt2 = 0; }
    __syncthreads();

    for (int i = tid; i < TOT/4; i += 1024) {
        float4 v = sc4[i];
        atomicAdd(&hist[fkey(v.x) >> 20], 1u);
        atomicAdd(&hist[fkey(v.y) >> 20], 1u);
        atomicAdd(&hist[fkey(v.z) >> 20], 1u);
        atomicAdd(&hist[fkey(v.w) >> 20], 1u);
    }
    __syncthreads();

    psum[tid] = hist[4*tid] + hist[4*tid+1] + hist[4*tid+2] + hist[4*tid+3];
    __syncthreads();

    if (tid == 0) {
        unsigned int acc = 0;
        int S = 0;
        for (int s = 31; s >= 0; --s) {
            unsigned int q = 0;
            for (int t = 0; t < 32; ++t) q += psum[s*32 + t];
            if (acc + q >= PRE) { S = s; break; }
            acc += q;
        }
        int Pb = S*32;
        for (int t = 31; t >= 0; --t) {
            unsigned int q = psum[S*32 + t];
            if (acc + q >= PRE) { Pb = S*32 + t; break; }
            acc += q;
        }
        unsigned int B = (unsigned int)(Pb*4);
        for (int b = 3; b >= 0; --b) {
            unsigned int q = hist[Pb*4 + b];
            if (acc + q >= PRE) { B = (unsigned int)(Pb*4 + b); break; }
            acc += q;
        }
        s_B = B;
        s_accAbove = acc;          // count strictly above bucket B
    }
    __syncthreads();

    const unsigned int B   = s_B;
    const unsigned int thr = B << 20;
    for (int i = tid; i < TOT/4; i += 1024) {
        float4 v = sc4[i];
        float vv[4] = {v.x, v.y, v.z, v.w};
#pragma unroll
        for (int c = 0; c < 4; ++c) {
            unsigned int k = fkey(vv[c]);
            if (k >= thr) {
                unsigned int pos = atomicAdd(&s_cnt, 1u);
                if (pos < CAND_MAX)
                    s_cand[pos] = ((unsigned long long)k << 32) |
                                  (unsigned int)(~(unsigned int)(4*i + c));
            }
        }
    }
    __syncthreads();

    const unsigned int cnt = min(s_cnt, (unsigned)CAND_MAX);
    unsigned long long* sortbuf = s_cand;
    int S_sort = 8192;

    if (cnt <= 4096u) {
        S_sort = 4096;
    } else {
        // ---- refine: 2nd-level hist on key bits [8,20) of boundary bucket --
        for (int b = tid; b < NBUCKET; b += 1024) hist[b] = 0;
        __syncthreads();
        for (int i = tid; i < (int)cnt; i += 1024) {
            unsigned int k = (unsigned int)(s_cand[i] >> 32);
            if ((k >> 20) == B) atomicAdd(&hist[(k >> 8) & 0xFFFu], 1u);
        }
        __syncthreads();
        psum[tid] = hist[4*tid] + hist[4*tid+1] + hist[4*tid+2] + hist[4*tid+3];
        __syncthreads();
        if (tid == 0) {
            unsigned int target = PRE - s_accAbove;   // >=1, <= hist total
            unsigned int acc = 0;
            int S = 0;
            for (int s = 31; s >= 0; --s) {
                unsigned int q = 0;
                for (int t = 0; t < 32; ++t) q += psum[s*32 + t];
                if (acc + q >= target) { S = s; break; }
                acc += q;
            }
            int Pb = S*32;
            for (int t = 31; t >= 0; --t) {
                unsigned int q = psum[S*32 + t];
                if (acc + q >= target) { Pb = S*32 + t; break; }
                acc += q;
            }
            unsigned int F = (unsigned int)(Pb*4);
            for (int b = 3; b >= 0; --b) {
                unsigned int q = hist[Pb*4 + b];
                if (acc + q >= target) { F = (unsigned int)(Pb*4 + b);
                                         acc += q; break; }
                acc += q;
            }
            s_F = F;
            s_newcnt = s_accAbove + acc;   // kept count after refinement
        }
        __syncthreads();

        if (s_newcnt <= 4096u) {
            const unsigned int F = s_F;
            for (int i = tid; i < (int)cnt; i += 1024) {
                unsigned long long c = s_cand[i];
                unsigned int k = (unsigned int)(c >> 32);
                unsigned int bk = k >> 20;
                bool keep = (bk > B) | ((bk == B) & (((k >> 8) & 0xFFFu) >= F));
                if (keep) {
                    unsigned int pos = atomicAdd(&s_cnt2, 1u);
                    s_cand2[pos] = c;
                }
            }
            __syncthreads();
            sortbuf = s_cand2;
            S_sort  = 4096;
            for (int i = (int)s_cnt2 + tid; i < 4096; i += 1024)
                s_cand2[i] = 0ull;
        } else {
            // pathological ties: sort all coarse candidates (8192)
            for (int i = (int)cnt + tid; i < 8192; i += 1024)
                s_cand[i] = 0ull;
        }
    }
    if (S_sort == 4096 && sortbuf == s_cand)
        for (int i = (int)cnt + tid; i < 4096; i += 1024) s_cand[i] = 0ull;
    __syncthreads();

    // bitonic sort, descending on u64 (ties: smaller idx first via ~idx)
    for (int k = 2; k <= S_sort; k <<= 1) {
        for (int j = k >> 1; j > 0; j >>= 1) {
            for (int i = tid; i < S_sort; i += 1024) {
                int ixj = i ^ j;
                if (ixj > i) {
                    unsigned long long a = sortbuf[i], b = sortbuf[ixj];
                    bool dir = (i & k) != 0;
                    if ((a < b) != dir) { sortbuf[i] = b; sortbuf[ixj] = a; }
                }
            }
            __syncthreads();
        }
    }

    // output scores + fused box gather-compute
    const float ratios_[3] = {0.5f, 1.0f, 2.0f};
    const float scales_[3] = {8.0f, 16.0f, 32.0f};
    for (int r = tid; r < PRE; r += 1024) {
        unsigned long long c = sortbuf[r];
        unsigned int key = (unsigned int)(c >> 32);
        int o = (int)(~(unsigned int)(c & 0xFFFFFFFFull));
        g_topk_score[n*PRE + r] = fkey_inv(key);

        const int kk = o % K_ANCH;
        const int t0 = o / K_ANCH;
        const int ww = t0 % Wdim;
        const int hh = t0 / Wdim;

        float v[4];
#pragma unroll
        for (int jj = 0; jj < 4; ++jj) {
            int f  = ((kk*4 + jj)*Hdim + hh)*Wdim + ww;
            int j  = f & 3;
            int r1 = f >> 2;
            int k  = r1 % K_ANCH;
            int r2 = r1 / K_ANCH;
            int w  = r2 % Wdim;
            int h  = r2 / Wdim;

            float sr  = __fsqrt_rn(ratios_[k/3]);
            float wsz = __fdiv_rn(__fmul_rn(16.0f, scales_[k%3]), sr);
            float hsz = __fmul_rn(__fmul_rn(16.0f, scales_[k%3]), sr);
            float cx  = __fmul_rn(__fadd_rn((float)w, 0.5f), 16.0f);
            float cy  = __fmul_rn(__fadd_rn((float)h, 0.5f), 16.0f);

            float a;
            if      (j == 0) a = __fsub_rn(cx, __fmul_rn(0.5f, wsz));
            else if (j == 1) a = __fsub_rn(cy, __fmul_rn(0.5f, hsz));
            else if (j == 2) a = __fadd_rn(cx, __fmul_rn(0.5f, wsz));
            else             a = __fadd_rn(cy, __fmul_rn(0.5f, hsz));

            float d   = deltas[((size_t)n*36 + (k*4 + j))*HW + h*Wdim + w];
            float val = __fadd_rn(a, d);
            v[jj] = fminf(fmaxf(val, 0.0f), 1919.0f);
        }
        g_boxes[n*PRE + r] = make_float4(v[0], v[1], v[2], v[3]);
    }
}

// ---------------- Stage 3: NMS suppression bitmask (R9-proven) --------------
extern "C" __global__ void __launch_bounds__(256)
mask_kernel() {
    const int cb = blockIdx.y, n = blockIdx.z;
    const int sub = threadIdx.x >> 6;            // 0..3
    const int t   = threadIdx.x & 63;
    const int rb  = blockIdx.x*4 + sub;
    __shared__ float4 colbox[64];
    __shared__ float  colarea[64];

    if (threadIdx.x < 64) {
        int cj = cb*64 + threadIdx.x;
        float4 cbx = (cj < PRE) ? g_boxes[n*PRE + cj] : make_float4(0,0,0,0);
        colbox[threadIdx.x]  = cbx;
        colarea[threadIdx.x] = boxarea(cbx);
    }
    __syncthreads();

    if (rb > cb || rb >= NWORDS) return;
    const int i = rb*64 + t;
    if (i >= PRE) return;

    const float4 bi = g_boxes[n*PRE + i];
    const float  ai = boxarea(bi);
    const int jmax = min(64, PRE - cb*64);
    unsigned long long bits = 0ull;
    const int cstart = (rb == cb) ? (t + 1) : 0;

    for (int c = cstart; c < jmax; ++c) {
        float4 bj = colbox[c];
        float aj = colarea[c];
        float xx1 = fmaxf(bi.x, bj.x), yy1 = fmaxf(bi.y, bj.y);
        float xx2 = fminf(bi.z, bj.z), yy2 = fminf(bi.w, bj.w);
        float iw = fmaxf(__fadd_rn(__fsub_rn(xx2, xx1), 1.0f), 0.0f);
        float ih = fmaxf(__fadd_rn(__fsub_rn(yy2, yy1), 1.0f), 0.0f);
        float inter = __fmul_rn(iw, ih);
        float denom = __fsub_rn(__fadd_rn(ai, aj), inter);
        if (iou_gt_half(inter, denom)) bits |= (1ull << c);
    }
    g_mask[((size_t)n*PRE + i)*MPITCH + cb] = bits;
}

// ---------------- Stage 4: lazy scan, 4 warps/batch --------------------------
// 128 threads: gather-OR over kept rows partitioned across all threads (full
// MLP), warp partials combined in smem; warp 0 runs the uniform intra-pair
// resolve from the ping-pong diagonal block (prefetched 1 row/thread).
extern "C" __global__ void __launch_bounds__(128)
scan_kernel(float* __restrict__ out) {
    const int n = blockIdx.x;
    const int tid  = threadIdx.x;
    const int lane = tid & 31;
    const int wid  = tid >> 5;
    __shared__ ulonglong2 s_diag[2][128];    // 4KB
    __shared__ ulonglong2 s_accw[4];
    __shared__ int s_kept[POST];
    __shared__ int s_nk;
    const unsigned FULL = 0xffffffffu;

    const unsigned long long* __restrict__ mbase =
        g_mask + (size_t)n * PRE * MPITCH;

    // preload diagonal block of pair 0 (one row per thread)
    s_diag[0][tid] = *(const ulonglong2*)(mbase + (size_t)tid * MPITCH);

    int nk = 0;
    for (int t = 0; t < NPAIR && nk < POST; ++t) {
        const int cb = t & 1, pb = cb ^ 1;
        const int w2 = 2*t;

        // prefetch diagonal block of pair t+1 (one row per thread)
        if (t + 1 < NPAIR) {
            int r = 128*(t+1) + tid;
            ulonglong2 d = make_ulonglong2(0ull, 0ull);
            if (r < PRE)
                d = *(const ulonglong2*)(mbase + (size_t)r * MPITCH + (w2+2));
            s_diag[pb][tid] = d;
        }

        // gather-OR partitioned over 128 threads (<=3 loads each, full MLP)
        unsigned long long gx = 0ull, gy = 0ull;
        for (int j = tid; j < nk; j += 128) {
            ulonglong2 m = *(const ulonglong2*)
                (mbase + (size_t)s_kept[j] * MPITCH + w2);
            gx |= m.x; gy |= m.y;
        }
#pragma unroll
        for (int off = 16; off; off >>= 1) {
            gx |= __shfl_xor_sync(FULL, gx, off);
            gy |= __shfl_xor_sync(FULL, gy, off);
        }
        if (lane == 0) s_accw[wid] = make_ulonglong2(gx, gy);
        __syncthreads();

        if (wid == 0) {
            unsigned long long a0 =
                s_accw[0].x | s_accw[1].x | s_accw[2].x | s_accw[3].x;
            unsigned long long a1 =
                s_accw[0].y | s_accw[1].y | s_accw[2].y | s_accw[3].y;
            unsigned long long f0 = (w2   == NWORDS-1) ? ((1ull<<56)-1ull)
                                  : (w2   <  NWORDS  ) ? ~0ull : 0ull;
            unsigned long long f1 = (w2+1 == NWORDS-1) ? ((1ull<<56)-1ull)
                                  : (w2+1 <  NWORDS  ) ? ~0ull : 0ull;
            unsigned long long c0 = f0 & ~a0;
            unsigned long long c1 = f1 & ~a1;

            const int base = 128*t;
            int k = nk;
            while ((c0 | c1) && k < POST) {
                if (c0) {
                    int b = __ffsll((long long)c0) - 1;
                    s_kept[k] = base + b;            // uniform write
                    ++k;
                    c0 &= ~(1ull << b);
                    ulonglong2 d = s_diag[cb][b];
                    c0 &= ~d.x;
                    c1 &= ~d.y;
                } else {
                    int b = __ffsll((long long)c1) - 1;
                    s_kept[k] = base + 64 + b;
                    ++k;
                    c1 &= ~(1ull << b);
                    ulonglong2 d = s_diag[cb][64 + b];
                    c1 &= ~d.y;
                }
            }
            if (lane == 0) s_nk = k;
        }
        __syncthreads();
        nk = s_nk;
    }

    for (int r = tid; r < POST; r += 128) {
        float x1 = 0.0f, y1 = 0.0f, x2 = 0.0f, y2 = 0.0f;
        if (r < nk) {
            int i = s_kept[r];
            float4 b = g_boxes[n*PRE + i];
            x1 = b.x; y1 = b.y; x2 = b.z; y2 = b.w;
        }
        float* o = out + (size_t)(n*POST + r)*5;
        o[1] = x1; o[2] = y1; o[3] = x2; o[4] = y2;
    }

    // batch 7 broadcasts its selected scores into column 0 of every batch
    if (n == 7) {
        for (int r = tid; r < POST; r += 128) {
            float sc = (r < nk) ? g_topk_score[7*PRE + s_kept[r]] : 0.0f;
#pragma unroll
            for (int nn = 0; nn < N_BATCH; ++nn)
                out[(size_t)(nn*POST + r)*5] = sc;
        }
    }
}

// ---------------- launch -----------------------------------------------------
extern "C" void kernel_launch(void* const* d_in, const int* in_sizes, int n_in,
                              void* d_out, int out_size) {
    const float* cls;
    const float* deltas;
    if (in_sizes[0] == N_BATCH*K_ANCH*HW) {     // 1,036,800
        cls = (const float*)d_in[0]; deltas = (const float*)d_in[1];
    } else {
        cls = (const float*)d_in[1]; deltas = (const float*)d_in[0];
    }
    float* out = (float*)d_out;

    cudaFuncSetAttribute(topk_kernel,
                         cudaFuncAttributeMaxDynamicSharedMemorySize, SMEM_DYN);

    topk_kernel<<<N_BATCH, 1024, SMEM_DYN>>>(cls, deltas);
    dim3 mg((NWORDS + 3)/4, NWORDS, N_BATCH);
    mask_kernel<<<mg, 256>>>();
    scan_kernel<<<N_BATCH, 128>>>(out);
}